// round 10
// baseline (speedup 1.0000x reference)
#include <cuda_runtime.h>
#include <cuda_bf16.h>
#include <cstdint>

typedef __nv_bfloat16 bf16;

#define TT 1024
#define BB 64
#define WW 512
#define W3 1536
#define GRID 128
#define NTH 512

// smem byte offsets (rows are 144B = 64 bf16 + 16B pad -> LDSM conflict-free)
#define SM_WHI 0                    // weights hi: 384 rows (kc*24+c) x 144B
#define SM_WLO 55296                // weights lo
#define SM_A   110592               // A: [buf2][hi/lo][64 rows x 144B] = 4 x 9216
#define SM_DI  147456               // partial D input-half: 64 x 26 fp32
#define SM_DH  154112               // partial D hidden-half
#define SM_RM  160768               // float[64]
#define SM_BIA 161056               // float[24] gate-major
#define SM_BHN 161152               // float[8]
#define SMEM_BYTES 161216

__device__ bf16 g_xHi[TT][BB][WW];
__device__ bf16 g_xLo[TT][BB][WW];
__device__ bf16 g_hHi[2][2][BB][WW];   // [layer][buf][b][w]
__device__ bf16 g_hLo[2][2][BB][WW];
__device__ float g_hF[2][2][BB][WW];
__device__ unsigned g_cnt = 0;
__device__ volatile unsigned g_gen = 0;
__device__ int g_reset_mode = 0;

__global__ void sniff_resets_kernel(const unsigned* __restrict__ r)
{
    __shared__ unsigned red[256];
    unsigned m = 0;
    for (int i = threadIdx.x; i < (TT * BB) / 4; i += 256) m = max(m, r[i]);
    red[threadIdx.x] = m;
    __syncthreads();
    for (int s = 128; s > 0; s >>= 1) {
        if (threadIdx.x < s) red[threadIdx.x] = max(red[threadIdx.x], red[threadIdx.x + s]);
        __syncthreads();
    }
    if (threadIdx.x == 0) {
        unsigned mx = red[0];
        g_reset_mode = (mx <= 1u) ? 1 : (mx >= 0x10000000u ? 2 : 0);
    }
}

__device__ __forceinline__ float reset_mask(const void* r, int mode, int idx)
{
    if (mode == 1) return ((const int*)r)[idx] != 0 ? 0.0f : 1.0f;
    if (mode == 2) return ((const float*)r)[idx] != 0.0f ? 0.0f : 1.0f;
    return ((const unsigned char*)r)[idx] != 0 ? 0.0f : 1.0f;
}

// split ins (fp32 [t][b][w]) into bf16 hi/lo, same layout
__global__ void split_ins_kernel(const float* __restrict__ ins)
{
    size_t i = ((size_t)blockIdx.x * 256 + threadIdx.x) * 4;
    bf16* xh = &g_xHi[0][0][0];
    bf16* xl = &g_xLo[0][0][0];
    float4 v = *(const float4*)(ins + i);
    const float f[4] = {v.x, v.y, v.z, v.w};
#pragma unroll
    for (int j = 0; j < 4; ++j) {
        bf16 h = __float2bfloat16(f[j]);
        xh[i + j] = h;
        xl[i + j] = __float2bfloat16(f[j] - __bfloat162float(h));
    }
}

__device__ __forceinline__ uint32_t smem_u32(const void* p)
{
    uint32_t a;
    asm("{ .reg .u64 t; cvta.to.shared.u64 t, %1; cvt.u32.u64 %0, t; }" : "=r"(a) : "l"(p));
    return a;
}

#define LDSM4(d, addr) asm volatile( \
    "ldmatrix.sync.aligned.m8n8.x4.shared.b16 {%0,%1,%2,%3},[%4];" \
    : "=r"((d)[0]), "=r"((d)[1]), "=r"((d)[2]), "=r"((d)[3]) : "r"(addr))
#define LDSM2(d, addr) asm volatile( \
    "ldmatrix.sync.aligned.m8n8.x2.shared.b16 {%0,%1},[%2];" \
    : "=r"((d)[0]), "=r"((d)[1]) : "r"(addr))
#define MMA(acc, A, B) asm volatile( \
    "mma.sync.aligned.m16n8k16.row.col.f32.bf16.bf16.f32 " \
    "{%0,%1,%2,%3},{%4,%5,%6,%7},{%8,%9},{%0,%1,%2,%3};" \
    : "+f"((acc)[0]), "+f"((acc)[1]), "+f"((acc)[2]), "+f"((acc)[3]) \
    : "r"((A)[0]), "r"((A)[1]), "r"((A)[2]), "r"((A)[3]), "r"((B)[0]), "r"((B)[1]))

// one 64-k chunk: 4 q-steps x (A hi/lo x4, B hi/lo x2 ldmatrix; hh+hl+lh mma)
__device__ __forceinline__ void chunk_mma(uint32_t aHiB, uint32_t aLoB,
                                          uint32_t bHiB, uint32_t bLoB, float acc[4])
{
#pragma unroll
    for (int q = 0; q < 4; ++q) {
        uint32_t ah[4], al[4], bh[2], bl[2];
        LDSM4(ah, aHiB + q * 32);
        LDSM4(al, aLoB + q * 32);
        LDSM2(bh, bHiB + q * 32);
        LDSM2(bl, bLoB + q * 32);
        MMA(acc, ah, bh);
        MMA(acc, ah, bl);
        MMA(acc, al, bh);
    }
}

__device__ __forceinline__ void stage(int kc, const bf16* iHi, const bf16* iLo,
                                      const bf16* hHi, const bf16* hLo,
                                      int buf, int tid, char* smem)
{
    const bf16* sHi = (kc < 8) ? iHi : hHi;
    const bf16* sLo = (kc < 8) ? iLo : hLo;
    const int koff = (kc & 7) * 64;
    const int b = tid >> 3, u = tid & 7;
    uint4 vh = __ldcg((const uint4*)(sHi + b * 512 + koff + u * 8));
    uint4 vl = __ldcg((const uint4*)(sLo + b * 512 + koff + u * 8));
    *(uint4*)(smem + SM_A + (buf * 2 + 0) * 9216 + b * 144 + u * 16) = vh;
    *(uint4*)(smem + SM_A + (buf * 2 + 1) * 9216 + b * 144 + u * 16) = vl;
}

__global__ void __launch_bounds__(NTH, 1)
gru_scan_kernel(const void* __restrict__ resets,
                const float* __restrict__ Wi, const float* __restrict__ bi,
                const float* __restrict__ Wh, const float* __restrict__ bhn,
                float* __restrict__ out)
{
    extern __shared__ char smem[];
    const uint32_t sbase = smem_u32(smem);
    float* rm   = (float*)(smem + SM_RM);
    float* bia  = (float*)(smem + SM_BIA);
    float* bhna = (float*)(smem + SM_BHN);
    float* DI   = (float*)(smem + SM_DI);
    float* DH   = (float*)(smem + SM_DH);

    const int tid  = threadIdx.x;
    const int lane = tid & 31;
    const int warp = tid >> 5;
    const int cta  = blockIdx.x;
    const int group = cta >> 6;          // 0: layer-1 task, 1: layer-0 task
    const int lyr  = group ? 0 : 1;      // layer this CTA computes
    const int gwBase = (cta & 63) * 8;   // 8 gate-triples per CTA
    const int rmode = g_reset_mode;

    // ---- one-time: weights to smem as bf16 hi/lo, [kc*24 + c] rows of 64 k ----
    // col order gate-major: c = gate*8 + ttl
    const float* WiL = Wi + (size_t)lyr * WW * W3;
    const float* WhL = Wh + (size_t)lyr * WW * W3;
    for (int idx = tid; idx < 24 * 1024; idx += NTH) {
        int c = idx % 24, k = idx / 24;
        int gate = c >> 3, ttl = c & 7;
        int gc = gwBase + ttl + gate * WW;
        float v = (k < WW) ? WiL[(size_t)k * W3 + gc] : WhL[(size_t)(k - WW) * W3 + gc];
        bf16 h = __float2bfloat16(v);
        bf16 l = __float2bfloat16(v - __bfloat162float(h));
        int off = (((k >> 6) * 24 + c) * 144) + (k & 63) * 2;
        *(bf16*)(smem + SM_WHI + off) = h;
        *(bf16*)(smem + SM_WLO + off) = l;
    }
    if (tid < 24) bia[tid] = bi[lyr * W3 + (tid >> 3) * WW + gwBase + (tid & 7)];
    if (tid < 8)  bhna[tid] = bhn[lyr * WW + gwBase + tid];

    unsigned gen = 0;
    if (tid == 0) gen = g_gen;
    __syncthreads();

    float* out_carry = out;
    float* out_ys    = out + 2 * BB * WW;

    // mma tile assignment: warps 0-11 compute; mt = rows mt*16.., nt = cols nt*8..
    const int mt = warp & 3, nt = warp >> 2;
    const bool wcompute = (warp < 12);
    // ldmatrix per-lane offsets
    const int sub = lane >> 3, r8 = lane & 7;
    const uint32_t aoff = (mt * 16 + r8 + (sub & 1) * 8) * 144 + (sub >> 1) * 16;
    const uint32_t boff = (nt * 8 + r8) * 144 + ((lane >> 3) & 1) * 16;

    for (int p = 0; p <= TT; ++p) {
        const bool active = group ? (p < TT) : (p >= 1);
        if (active) {
            const int t = group ? p : (p - 1);
            const int hbuf = (p - 1) & 1;
            const bool zeroH = group ? (p == 0) : (p == 1);
            const bf16* iHi = group ? &g_xHi[t][0][0] : &g_hHi[0][hbuf][0][0];
            const bf16* iLo = group ? &g_xLo[t][0][0] : &g_hLo[0][hbuf][0][0];
            const bf16* hHi = &g_hHi[lyr][hbuf][0][0];
            const bf16* hLo = &g_hLo[lyr][hbuf][0][0];
            const float* hF = &g_hF[lyr][hbuf][0][0];

            if (tid < BB)
                rm[tid] = zeroH ? 0.0f : reset_mask(resets, rmode, t * BB + tid);

            float accI[4] = {0, 0, 0, 0}, accH[4] = {0, 0, 0, 0};

            stage(0, iHi, iLo, hHi, hLo, 0, tid, smem);
            __syncthreads();

            for (int kc = 0; kc < 16; ++kc) {
                const int buf = kc & 1;
                if (kc + 1 < 16)
                    stage(kc + 1, iHi, iLo, hHi, hLo, buf ^ 1, tid, smem);
                if (wcompute) {
                    uint32_t aHiB = sbase + SM_A + (buf * 2) * 9216 + aoff;
                    uint32_t bHiB = sbase + SM_WHI + kc * 3456 + boff;
                    if (kc < 8) chunk_mma(aHiB, aHiB + 9216, bHiB, bHiB + 55296, accI);
                    else        chunk_mma(aHiB, aHiB + 9216, bHiB, bHiB + 55296, accH);
                }
                __syncthreads();
            }

            // dump mma tiles to smem partials
            if (wcompute) {
                const int r = lane >> 2, cc = (lane & 3) * 2;
                const int b0 = (mt * 16 + r) * 26 + nt * 8 + cc;
                const int b1 = (mt * 16 + r + 8) * 26 + nt * 8 + cc;
                DI[b0] = accI[0]; DI[b0 + 1] = accI[1];
                DI[b1] = accI[2]; DI[b1 + 1] = accI[3];
                DH[b0] = accH[0]; DH[b0 + 1] = accH[1];
                DH[b1] = accH[2]; DH[b1 + 1] = accH[3];
            }
            __syncthreads();

            // epilogue: 512 threads, one (b, ttl) each
            const int b = tid >> 3, ttl = tid & 7;
            const float m = rm[b];
            const float sir = DI[b * 26 + ttl],      shr = DH[b * 26 + ttl];
            const float siz = DI[b * 26 + 8 + ttl],  shz = DH[b * 26 + 8 + ttl];
            const float sin_ = DI[b * 26 + 16 + ttl], shn = DH[b * 26 + 16 + ttl];
            const float r = 1.0f / (1.0f + __expf(-(bia[ttl] + sir + m * shr)));
            const float z = 1.0f / (1.0f + __expf(-(bia[8 + ttl] + siz + m * shz)));
            const float n = tanhf(bia[16 + ttl] + sin_ + r * (m * shn + bhna[ttl]));
            const int w = gwBase + ttl;
            const float hp = m * __ldcg(hF + b * 512 + w);
            const float h = (1.0f - z) * n + z * hp;

            const int pb = p & 1;
            bf16 hh = __float2bfloat16(h);
            g_hF [lyr][pb][b][w] = h;
            g_hHi[lyr][pb][b][w] = hh;
            g_hLo[lyr][pb][b][w] = __float2bfloat16(h - __bfloat162float(hh));
            if (group == 0) {
                out_ys[(size_t)t * BB * WW + b * WW + w] = h;
                if (p == TT) out_carry[BB * WW + b * WW + w] = h;
            } else if (p == TT - 1) {
                out_carry[b * WW + w] = h;
            }
        }

        // grid barrier
        __syncthreads();
        if (tid == 0) {
            __threadfence();
            unsigned a = atomicAdd(&g_cnt, 1);
            gen += 1;
            if (a == GRID - 1) {
                g_cnt = 0;
                __threadfence();
                g_gen = gen;
            } else {
                while (g_gen < gen) { __nanosleep(20); }
                __threadfence();
            }
        }
        __syncthreads();
    }
}

extern "C" void kernel_launch(void* const* d_in, const int* in_sizes, int n_in,
                              void* d_out, int out_size)
{
    const float* ins    = (const float*)d_in[0];
    const void*  resets = (const void*)d_in[1];
    const float* Wi     = (const float*)d_in[2];
    const float* bi     = (const float*)d_in[3];
    const float* Wh     = (const float*)d_in[4];
    const float* bhn    = (const float*)d_in[5];
    float*       out    = (float*)d_out;

    sniff_resets_kernel<<<1, 256>>>((const unsigned*)resets);
    split_ins_kernel<<<(TT * BB * WW) / 1024, 256>>>(ins);

    cudaFuncSetAttribute(gru_scan_kernel,
                         cudaFuncAttributeMaxDynamicSharedMemorySize, SMEM_BYTES);
    gru_scan_kernel<<<GRID, NTH, SMEM_BYTES>>>(resets, Wi, bi, Wh, bhn, out);
}

// round 12
// speedup vs baseline: 1.6063x; 1.6063x over previous
#include <cuda_runtime.h>
#include <cuda_bf16.h>
#include <cstdint>

typedef __nv_bfloat16 bf16;

#define TT 1024
#define BB 64
#define WW 512
#define W3 1536
#define GRID 128
#define NTH 256

// smem layout (bytes)
#define SM_RM   0
#define SM_BIA  256
#define SM_BHN  384
#define SM_WSTG 1024                 // weights staging hi(55296)+lo(55296), init-only
#define SM_PART 1024                 // 8 x 64 x 24 fp32 = 49152 -> ends 50176
#define SM_A    50176                // 8 warps x 4 bufs x 5120B = 163840
#define SMEM_BYTES 214016

__device__ __align__(128) bf16 g_xHi[TT][BB][WW];
__device__ __align__(128) bf16 g_xLo[TT][BB][WW];
__device__ __align__(128) bf16 g_hHi[2][2][BB][WW];   // [layer][buf][b][w]
__device__ __align__(128) bf16 g_hLo[2][2][BB][WW];
__device__ __align__(128) float g_hF[2][2][BB][WW];
__device__ unsigned g_cnt = 0;
__device__ volatile unsigned g_gen = 0;
__device__ int g_reset_mode = 0;

__global__ void sniff_resets_kernel(const unsigned* __restrict__ r)
{
    __shared__ unsigned red[256];
    unsigned m = 0;
    for (int i = threadIdx.x; i < (TT * BB) / 4; i += 256) m = max(m, r[i]);
    red[threadIdx.x] = m;
    __syncthreads();
    for (int s = 128; s > 0; s >>= 1) {
        if (threadIdx.x < s) red[threadIdx.x] = max(red[threadIdx.x], red[threadIdx.x + s]);
        __syncthreads();
    }
    if (threadIdx.x == 0) {
        unsigned mx = red[0];
        g_reset_mode = (mx <= 1u) ? 1 : (mx >= 0x10000000u ? 2 : 0);
    }
}

__device__ __forceinline__ float reset_mask(const void* r, int mode, int idx)
{
    if (mode == 1) return ((const int*)r)[idx] != 0 ? 0.0f : 1.0f;
    if (mode == 2) return ((const float*)r)[idx] != 0.0f ? 0.0f : 1.0f;
    return ((const unsigned char*)r)[idx] != 0 ? 0.0f : 1.0f;
}

__global__ void split_ins_kernel(const float* __restrict__ ins)
{
    size_t i = ((size_t)blockIdx.x * 256 + threadIdx.x) * 4;
    float4 v = *(const float4*)(ins + i);
    const float f[4] = {v.x, v.y, v.z, v.w};
    bf16* xh = &g_xHi[0][0][0];
    bf16* xl = &g_xLo[0][0][0];
#pragma unroll
    for (int j = 0; j < 4; ++j) {
        bf16 h = __float2bfloat16(f[j]);
        xh[i + j] = h;
        xl[i + j] = __float2bfloat16(f[j] - __bfloat162float(h));
    }
}

__device__ __forceinline__ uint32_t smem_u32(const void* p)
{
    uint32_t a;
    asm("{ .reg .u64 t; cvta.to.shared.u64 t, %1; cvt.u32.u64 %0, t; }" : "=r"(a) : "l"(p));
    return a;
}

#define LDSM4(d, addr) asm volatile( \
    "ldmatrix.sync.aligned.m8n8.x4.shared.b16 {%0,%1,%2,%3},[%4];" \
    : "=r"((d)[0]), "=r"((d)[1]), "=r"((d)[2]), "=r"((d)[3]) : "r"(addr))
#define LDSM2(d, addr) asm volatile( \
    "ldmatrix.sync.aligned.m8n8.x2.shared.b16 {%0,%1},[%2];" \
    : "=r"((d)[0]), "=r"((d)[1]) : "r"(addr))
#define MMA(acc, A, B) asm volatile( \
    "mma.sync.aligned.m16n8k16.row.col.f32.bf16.bf16.f32 " \
    "{%0,%1,%2,%3},{%4,%5,%6,%7},{%8,%9},{%0,%1,%2,%3};" \
    : "+f"((acc)[0]), "+f"((acc)[1]), "+f"((acc)[2]), "+f"((acc)[3]) \
    : "r"((A)[0]), "r"((A)[1]), "r"((A)[2]), "r"((A)[3]), "r"((B)[0]), "r"((B)[1]))

// stage one 16-k sub-chunk (64 rows, hi+lo) into this warp's private ring buffer
__device__ __forceinline__ void stage_sub(const bf16* sH, const bf16* sL, int kk,
                                          uint32_t db, int srow, int shalf)
{
#pragma unroll
    for (int a2 = 0; a2 < 4; ++a2) {
        int rr = a2 * 16 + srow;
        uint32_t d = db + rr * 80 + shalf * 16;
        const bf16* ph = sH + rr * 512 + kk + shalf * 8;
        const bf16* pl = sL + rr * 512 + kk + shalf * 8;
        asm volatile("cp.async.cg.shared.global [%0],[%1],16;\n\t"
                     "cp.async.cg.shared.global [%2],[%3],16;"
                     :: "r"(d), "l"(ph), "r"(d + 32), "l"(pl) : "memory");
    }
    asm volatile("cp.async.commit_group;" ::: "memory");
}

__global__ void __launch_bounds__(NTH, 1)
gru_scan_kernel(const void* __restrict__ resets,
                const float* __restrict__ Wi, const float* __restrict__ bi,
                const float* __restrict__ Wh, const float* __restrict__ bhn,
                float* __restrict__ out)
{
    extern __shared__ char smem[];
    const uint32_t sbase = smem_u32(smem);
    float* rm   = (float*)(smem + SM_RM);
    float* bia  = (float*)(smem + SM_BIA);
    float* bhna = (float*)(smem + SM_BHN);
    float* part = (float*)(smem + SM_PART);

    const int tid = threadIdx.x, lane = tid & 31, warp = tid >> 5;  // warp 0..7 = K-slice
    const int cta = blockIdx.x, group = cta >> 6, lyr = group ? 0 : 1;
    const int gwBase = (cta & 63) * 8;
    const int rmode = g_reset_mode;
    const int r8 = lane & 7, g4 = lane >> 3;

    // ---- init: weights (bf16 hi/lo) into staging smem: rows (k>>6)*24+c x 144B ----
    const float* WiL = Wi + (size_t)lyr * WW * W3;
    const float* WhL = Wh + (size_t)lyr * WW * W3;
    for (int idx = tid; idx < 24 * 1024; idx += NTH) {
        int c = idx % 24, k = idx / 24;
        int gc = gwBase + (c & 7) + (c >> 3) * WW;
        float v = (k < WW) ? WiL[(size_t)k * W3 + gc] : WhL[(size_t)(k - WW) * W3 + gc];
        bf16 h = __float2bfloat16(v);
        bf16 l = __float2bfloat16(v - __bfloat162float(h));
        int off = ((k >> 6) * 24 + c) * 144 + (k & 63) * 2;
        *(bf16*)(smem + SM_WSTG + off) = h;
        *(bf16*)(smem + SM_WSTG + 55296 + off) = l;
    }
    if (tid < 24) bia[tid] = bi[lyr * W3 + (tid >> 3) * WW + gwBase + (tid & 7)];
    if (tid < 8)  bhna[tid] = bhn[lyr * WW + gwBase + tid];
    unsigned gen = 0;
    if (tid == 0) gen = g_gen;
    __syncthreads();

    // ---- load persistent B fragments (hi/lo) for this warp's K=128 slice ----
    uint32_t bfr[3][8][2][2];
#pragma unroll
    for (int nt = 0; nt < 3; ++nt)
#pragma unroll
        for (int j = 0; j < 8; ++j) {
            int kc = warp * 2 + (j >> 2), q = j & 3;
            uint32_t ba = sbase + SM_WSTG + kc * 3456 +
                          (nt * 8 + r8) * 144 + (g4 & 1) * 16 + q * 32;
            LDSM2(bfr[nt][j][0], ba);
            LDSM2(bfr[nt][j][1], ba + 55296);
        }
    __syncthreads();   // weight staging area now reusable as A/part

    const uint32_t awb = sbase + SM_A + warp * 20480;   // 4 bufs x 5120
    const uint32_t aoff = ((g4 & 1) * 8 + r8) * 80 + (g4 >> 1) * 16;
    const int k0 = (warp & 3) * 128;                    // k base within half
    const int srow = lane >> 1, shalf = lane & 1;

    float* out_carry = out;
    float* out_ys    = out + 2 * BB * WW;

#pragma unroll 1
    for (int p = 0; p <= TT; ++p) {
        const bool active = group ? (p < TT) : (p >= 1);
        const int t = group ? p : (p - 1);
        const int hbuf = (p - 1) & 1;
        if (active) {
            const bool zeroH = group ? (p == 0) : (p == 1);
            const bf16* iHi = group ? &g_xHi[t][0][0] : &g_hHi[0][hbuf][0][0];
            const bf16* iLo = group ? &g_xLo[t][0][0] : &g_hLo[0][hbuf][0][0];
            const bf16* sH = (warp < 4) ? iHi : &g_hHi[lyr][hbuf][0][0];
            const bf16* sL = (warp < 4) ? iLo : &g_hLo[lyr][hbuf][0][0];

            if (tid < BB)
                rm[tid] = zeroH ? 0.0f : reset_mask(resets, rmode, t * BB + tid);

            float acc[4][3][4];
#pragma unroll
            for (int mt = 0; mt < 4; ++mt)
#pragma unroll
                for (int nt = 0; nt < 3; ++nt)
#pragma unroll
                    for (int q = 0; q < 4; ++q) acc[mt][nt][q] = 0.0f;

            stage_sub(sH, sL, k0 + 0 * 16, awb + 0 * 5120, srow, shalf);
            stage_sub(sH, sL, k0 + 1 * 16, awb + 1 * 5120, srow, shalf);
            stage_sub(sH, sL, k0 + 2 * 16, awb + 2 * 5120, srow, shalf);

#pragma unroll
            for (int s = 0; s < 8; ++s) {
                if (s < 6)       asm volatile("cp.async.wait_group 2;" ::: "memory");
                else if (s == 6) asm volatile("cp.async.wait_group 1;" ::: "memory");
                else             asm volatile("cp.async.wait_group 0;" ::: "memory");
                __syncwarp();
                const uint32_t ab = awb + (s & 3) * 5120 + aoff;
#pragma unroll
                for (int mt = 0; mt < 4; ++mt) {
                    uint32_t ah[4], al[4];
                    LDSM4(ah, ab + mt * 1280);
                    LDSM4(al, ab + mt * 1280 + 32);
#pragma unroll
                    for (int nt = 0; nt < 3; ++nt) {
                        MMA(acc[mt][nt], ah, bfr[nt][s][0]);
                        MMA(acc[mt][nt], ah, bfr[nt][s][1]);
                        MMA(acc[mt][nt], al, bfr[nt][s][0]);
                    }
                }
                if (s < 5)
                    stage_sub(sH, sL, k0 + (s + 3) * 16, awb + ((s + 3) & 3) * 5120,
                              srow, shalf);
            }

            // dump this warp's 64x24 partial tile
            float* prt = part + warp * 1536;
            const int dr = lane >> 2, dc = (lane & 3) * 2;
#pragma unroll
            for (int mt = 0; mt < 4; ++mt)
#pragma unroll
                for (int nt = 0; nt < 3; ++nt) {
                    int b0 = (mt * 16 + dr) * 24 + nt * 8 + dc;
                    *(float2*)(prt + b0)       = make_float2(acc[mt][nt][0], acc[mt][nt][1]);
                    *(float2*)(prt + b0 + 192) = make_float2(acc[mt][nt][2], acc[mt][nt][3]);
                }
        }

        __syncthreads();

        if (active) {
            const float* hF = &g_hF[lyr][hbuf][0][0];
            const int pb = p & 1;
#pragma unroll
            for (int e = 0; e < 2; ++e) {
                const int idx = tid + e * 256;
                const int b = idx >> 3, ttl = idx & 7;
                const float m = rm[b];
                float si[3], sh[3];
#pragma unroll
                for (int g = 0; g < 3; ++g) {
                    const int c = g * 8 + ttl;
                    float a0 = 0.0f, a1 = 0.0f;
#pragma unroll
                    for (int w8 = 0; w8 < 4; ++w8) {
                        a0 += part[w8 * 1536 + b * 24 + c];
                        a1 += part[(w8 + 4) * 1536 + b * 24 + c];
                    }
                    si[g] = a0; sh[g] = a1;
                }
                const float r = 1.0f / (1.0f + __expf(-(bia[ttl] + si[0] + m * sh[0])));
                const float z = 1.0f / (1.0f + __expf(-(bia[8 + ttl] + si[1] + m * sh[1])));
                const float n = tanhf(bia[16 + ttl] + si[2] + r * (m * sh[2] + bhna[ttl]));
                const int w = gwBase + ttl;
                const float hp = m * __ldcg(hF + b * 512 + w);
                const float h = (1.0f - z) * n + z * hp;
                bf16 hh = __float2bfloat16(h);
                g_hF [lyr][pb][b][w] = h;
                g_hHi[lyr][pb][b][w] = hh;
                g_hLo[lyr][pb][b][w] = __float2bfloat16(h - __bfloat162float(hh));
                if (group == 0) {
                    out_ys[(size_t)t * BB * WW + b * WW + w] = h;
                    if (p == TT) out_carry[BB * WW + b * WW + w] = h;
                } else if (p == TT - 1) {
                    out_carry[b * WW + w] = h;
                }
            }
        }

        // grid barrier
        __syncthreads();
        if (tid == 0) {
            __threadfence();
            unsigned a = atomicAdd(&g_cnt, 1);
            gen += 1;
            if (a == GRID - 1) {
                g_cnt = 0;
                __threadfence();
                g_gen = gen;
            } else {
                while (g_gen < gen) { __nanosleep(20); }
                __threadfence();
            }
        }
        __syncthreads();
    }
}

extern "C" void kernel_launch(void* const* d_in, const int* in_sizes, int n_in,
                              void* d_out, int out_size)
{
    const float* ins    = (const float*)d_in[0];
    const void*  resets = (const void*)d_in[1];
    const float* Wi     = (const float*)d_in[2];
    const float* bi     = (const float*)d_in[3];
    const float* Wh     = (const float*)d_in[4];
    const float* bhn    = (const float*)d_in[5];
    float*       out    = (float*)d_out;

    sniff_resets_kernel<<<1, 256>>>((const unsigned*)resets);
    split_ins_kernel<<<(TT * BB * WW) / 1024, 256>>>(ins);

    cudaFuncSetAttribute(gru_scan_kernel,
                         cudaFuncAttributeMaxDynamicSharedMemorySize, SMEM_BYTES);
    gru_scan_kernel<<<GRID, NTH, SMEM_BYTES>>>(resets, Wi, bi, Wh, bhn, out);
}